// round 7
// baseline (speedup 1.0000x reference)
#include <cuda_runtime.h>

// ---------------------------------------------------------------------------
// 4-level DWT lowpass analysis + synthesis, season = x - trend.
// FUSED: analysis levels (1,2) and (3,4) each become one 22-tap stride-4
// correlation; synthesis levels (1,2) and (3,4) each become one 4-phase
// up-4 composite (<=6 taps/phase). Pipeline: x ->A-> lo2 ->A-> lo4 ->S-> S2
// ->S-> trend.  4 stages, 3 barriers, 41KB SMEM => 512-thread CTAs, 4/SM,
// all 512 rows resident in a single wave.
//
// Exactness: every reference truncation equals the filter's natural support
// (analysis lengths 16387/8197/4102/2054; synthesis trims 8198->8197 and
// 16388->16387 drop samples that are never read), so zero-extended fusion is
// mathematically identical (fp reassociation ~1e-7 << 1e-3 tolerance).
// ---------------------------------------------------------------------------

#define THREADS 512

__host__ __device__ constexpr double Dv(int k) {
    return k == 0 ? -0.010597401784997278
         : k == 1 ?  0.032883011666982945
         : k == 2 ?  0.030841381835986965
         : k == 3 ? -0.18703481171888114
         : k == 4 ? -0.02798376941698385
         : k == 5 ?  0.6308807679295904
         : k == 6 ?  0.7148465705525415
         :           0.23037781330885523;
}

// Fused 2-level analysis: lo2[n] = sum_{j=0..21} CA(j) * in[4n+j-18]
// (in zero-extended).  CA(j) = sum_m h'[m] h'[j-2m],  h'[t] = DEC_LO[7-t].
__host__ __device__ constexpr float CA(int j) {
    double s = 0.0;
    for (int m = 0; m < 8; ++m) {
        const int k = j - 2 * m;
        if (k >= 0 && k < 8) s += Dv(7 - m) * Dv(7 - k);
    }
    return (float)s;
}

// Fused 2-level synthesis: out[4u+v] = sum_{p=0..5} GS(v,p) * in[u+p]
__host__ __device__ constexpr float GS(int v, int p) {
    const int w = v >> 1, e = v & 1;
    double s = 0.0;
    for (int i = 0; i < 4; ++i) {
        const int eps = (w + i) & 1, f = (w + i) >> 1;
        for (int j = 0; j < 4; ++j)
            if (f + j == p) s += Dv(2 * i + 1 - e) * Dv(2 * j + 1 - eps);
    }
    return (float)s;
}

__device__ __forceinline__ float lane(const float4 v, int l) {
    return l == 0 ? v.x : l == 1 ? v.y : l == 2 ? v.z : v.w;
}

// SMEM layout (floats), all bases 16B aligned:
//  [0,     4128)  E plane of lo2 (front pad 12; E = sm+12; valid E[0..4098])
//  [4128,  8256)  O plane of lo2 (front pad 12; O = sm+4140; valid O[0..4097])
//  [8256, 10320)  lo4 natural order (valid [0..2053], zero tail to 2063)
//  S2 (8200 used) reuses [0, 8208) after lo2 is dead.
#define E_OFF   12
#define O_OFF   4140
#define LO4_OFF 8256
#define SMEM_FLOATS 10320
#define SMEM_BYTES  (SMEM_FLOATS * 4)

__global__ __launch_bounds__(THREADS, 4)
void wt_decomp_kernel(const float* __restrict__ x,
                      float* __restrict__ season,
                      float* __restrict__ trend) {
    extern __shared__ float sm[];
    float* E   = sm + E_OFF;
    float* O   = sm + O_OFF;
    float* lo4 = sm + LO4_OFF;
    float* S2  = sm;                       // reuse of lo2 region after stage B

    const size_t off = (size_t)blockIdx.x * 32768;
    const float* xr = x + off;
    const int tid = threadIdx.x;

    // Zero pads (fronts, tails). Races with spurious stage-A zero writes are
    // same-value and benign.
    if (tid < 12) { sm[tid] = 0.f; sm[4128 + tid] = 0.f; }        // E,O fronts
    if (tid < 17) sm[4111 + tid] = 0.f;                           // E[4099..4115]
    if (tid < 18) sm[8238 + tid] = 0.f;                           // O[4098..4115]
    if (tid < 10) sm[10310 + tid] = 0.f;                          // lo4[2054..2063]

    // ---- Stage A: x (GMEM) -> lo2 (E/O planes), 8197 outputs, 2050 chunks --
    for (int c = tid; c < 2050; c += THREADS) {
        float a[4] = {0.f, 0.f, 0.f, 0.f};
        if (c >= 2 && c <= 2047) {
            const float4* xw = reinterpret_cast<const float4*>(xr + 16 * c - 20);
            #pragma unroll
            for (int s = 0; s < 9; ++s) {
                const float4 v = xw[s];
                #pragma unroll
                for (int l = 0; l < 4; ++l) {
                    const int t = 4 * s + l;          // value = x[16c-20+t]
                    #pragma unroll
                    for (int r = 0; r < 4; ++r) {
                        const int j = t - 2 - 4 * r;  // tap index for acc r
                        if (j >= 0 && j < 22)
                            a[r] = fmaf(lane(v, l), CA(j), a[r]);
                    }
                }
            }
        } else {
            #pragma unroll
            for (int r = 0; r < 4; ++r) {
                const int n = 4 * c + r;
                float acc = 0.f;
                #pragma unroll
                for (int j = 0; j < 22; ++j) {
                    const int idx = 4 * n + j - 18;
                    if (idx >= 0 && idx < 32768) acc = fmaf(xr[idx], CA(j), acc);
                }
                a[r] = acc;
            }
        }
        // lo2[4c..4c+3] -> E[2c],O[2c],E[2c+1],O[2c+1]
        *reinterpret_cast<float2*>(E + 2 * c) = make_float2(a[0], a[2]);
        *reinterpret_cast<float2*>(O + 2 * c) = make_float2(a[1], a[3]);
    }
    __syncthreads();

    // ---- Stage B: lo2 (planes) -> lo4 (natural), 2054 outputs, 514 chunks --
    for (int c = tid; c < 514; c += THREADS) {
        float a[4] = {0.f, 0.f, 0.f, 0.f};
        #pragma unroll
        for (int s = 0; s < 5; ++s) {
            const float4 ve = *reinterpret_cast<const float4*>(E + 8 * c - 12 + 4 * s);
            #pragma unroll
            for (int l = 0; l < 4; ++l) {
                const int d = -12 + 4 * s + l;        // E element offset from 8c
                #pragma unroll
                for (int r = 0; r < 4; ++r) {
                    const int j = 2 * d - 4 * r + 18; // even tap
                    if (j >= 0 && j < 22)
                        a[r] = fmaf(lane(ve, l), CA(j), a[r]);
                }
            }
            const float4 vo = *reinterpret_cast<const float4*>(O + 8 * c - 12 + 4 * s);
            #pragma unroll
            for (int l = 0; l < 4; ++l) {
                const int d = -12 + 4 * s + l;
                #pragma unroll
                for (int r = 0; r < 4; ++r) {
                    const int j = 2 * d - 4 * r + 19; // odd tap
                    if (j >= 0 && j < 22)
                        a[r] = fmaf(lane(vo, l), CA(j), a[r]);
                }
            }
        }
        *reinterpret_cast<float4*>(lo4 + 4 * c) = make_float4(a[0], a[1], a[2], a[3]);
    }
    __syncthreads();

    // ---- Stage C: lo4 -> S2 (8197 valid), 1025 chunks of 8 outputs ---------
    for (int c = tid; c < 1025; c += THREADS) {
        float ld[8];
        #pragma unroll
        for (int s = 0; s < 4; ++s)
            *reinterpret_cast<float2*>(ld + 2 * s) =
                *reinterpret_cast<const float2*>(lo4 + 2 * c + 2 * s);
        float o[8];
        #pragma unroll
        for (int w2 = 0; w2 < 2; ++w2)
            #pragma unroll
            for (int v = 0; v < 4; ++v) {
                float acc = 0.f;
                #pragma unroll
                for (int p = 0; p < 6; ++p)
                    if (!(v < 2 && p == 5))
                        acc = fmaf(ld[w2 + p], GS(v, p), acc);
                o[4 * w2 + v] = acc;
            }
        *reinterpret_cast<float4*>(S2 + 8 * c)     = make_float4(o[0], o[1], o[2], o[3]);
        *reinterpret_cast<float4*>(S2 + 8 * c + 4) = make_float4(o[4], o[5], o[6], o[7]);
    }
    __syncthreads();

    // ---- Stage D: S2 -> trend/season (GMEM), 4096 chunks of 8 outputs ------
    float* tre = trend + off;
    float* sea = season + off;
    for (int c = tid; c < 4096; c += THREADS) {
        float ld[8];
        #pragma unroll
        for (int s = 0; s < 4; ++s)
            *reinterpret_cast<float2*>(ld + 2 * s) =
                *reinterpret_cast<const float2*>(S2 + 2 * c + 2 * s);
        float o[8];
        #pragma unroll
        for (int w2 = 0; w2 < 2; ++w2)
            #pragma unroll
            for (int v = 0; v < 4; ++v) {
                float acc = 0.f;
                #pragma unroll
                for (int p = 0; p < 6; ++p)
                    if (!(v < 2 && p == 5))
                        acc = fmaf(ld[w2 + p], GS(v, p), acc);
                o[4 * w2 + v] = acc;
            }
        const int n0 = 8 * c;
        const float4 t0 = make_float4(o[0], o[1], o[2], o[3]);
        const float4 t1 = make_float4(o[4], o[5], o[6], o[7]);
        *reinterpret_cast<float4*>(tre + n0)     = t0;
        *reinterpret_cast<float4*>(tre + n0 + 4) = t1;
        const float4 x0 = __ldg(reinterpret_cast<const float4*>(xr + n0));
        const float4 x1 = __ldg(reinterpret_cast<const float4*>(xr + n0 + 4));
        *reinterpret_cast<float4*>(sea + n0) =
            make_float4(x0.x - t0.x, x0.y - t0.y, x0.z - t0.z, x0.w - t0.w);
        *reinterpret_cast<float4*>(sea + n0 + 4) =
            make_float4(x1.x - t1.x, x1.y - t1.y, x1.z - t1.z, x1.w - t1.w);
    }
}

extern "C" void kernel_launch(void* const* d_in, const int* in_sizes, int n_in,
                              void* d_out, int out_size) {
    (void)n_in; (void)out_size;
    const float* x = (const float*)d_in[0];
    float* out = (float*)d_out;

    const int nsig = in_sizes[0] / 32768;
    const size_t total = (size_t)nsig * 32768;
    float* season = out;            // output tuple order: (season, trend)
    float* trend  = out + total;

    wt_decomp_kernel<<<nsig, THREADS, SMEM_BYTES>>>(x, season, trend);
}